// round 15
// baseline (speedup 1.0000x reference)
#include <cuda_runtime.h>
#include <cuda_fp16.h>

#define HD   128
#define HD4  32
#define MAXN 50000
#define MAXE 800000
#define AS   136
#define BS   136
#define NSLOT 12

// ---------------- scratch ------------------------------------------------------
static __device__ float  g_B[6][(size_t)MAXN * HD];
static __device__ float2 g_ed[MAXN];
static __device__ float  g_degu[MAXN];
static __device__ float  g_degc[MAXN];
static __device__ float  g_dego[MAXN];
static __device__ float  g_stats[2 * NSLOT * HD];
// CSR (g_cnt2 is self-zeroing: scanfin clears it for the next graph replay)
static __device__ int    g_cnt2[2 * MAXN];
static __device__ int    g_rowptr[MAXN + 1];
static __device__ int    g_cursor[MAXN];
static __device__ int    g_er[MAXE];
static __device__ int    g_bsum[64];

struct GJob {
    const void* X; __half* Y; const float* W; const float* b;
    const float* sSin; const float* sQin; float* sSout; float* sQout;
};
struct GJobs { GJob j[3]; };
struct LJob {
    const __half* Z; float* out; const float* W; const float* b;
    const float* sSin; const float* sQin;
};
struct LJobs { LJob j[3]; };

__device__ __forceinline__ unsigned s2u(const void* p) {
    return (unsigned)__cvta_generic_to_shared(p);
}
__device__ __forceinline__ void ldsm_x4(unsigned* a, unsigned addr) {
    asm volatile("ldmatrix.sync.aligned.m8n8.x4.shared.b16 {%0,%1,%2,%3}, [%4];"
                 : "=r"(a[0]), "=r"(a[1]), "=r"(a[2]), "=r"(a[3]) : "r"(addr));
}
__device__ __forceinline__ void ldsm_x2t(unsigned* b, unsigned addr) {
    asm volatile("ldmatrix.sync.aligned.m8n8.x2.trans.shared.b16 {%0,%1}, [%2];"
                 : "=r"(b[0]), "=r"(b[1]) : "r"(addr));
}
__device__ __forceinline__ void mma_f16(float* c, const unsigned* a, const unsigned* b) {
    asm volatile(
        "mma.sync.aligned.m16n8k16.row.col.f32.f16.f16.f32 "
        "{%0,%1,%2,%3}, {%4,%5,%6,%7}, {%8,%9}, {%0,%1,%2,%3};"
        : "+f"(c[0]), "+f"(c[1]), "+f"(c[2]), "+f"(c[3])
        : "r"(a[0]), "r"(a[1]), "r"(a[2]), "r"(a[3]), "r"(b[0]), "r"(b[1]));
}
__device__ __forceinline__ void fma8(float* a, uint4 u, float nn) {
    __half2* h = (__half2*)&u;
#pragma unroll
    for (int j = 0; j < 4; j++) {
        float2 f = __half22float2(h[j]);
        a[2*j]   += f.x * nn;
        a[2*j+1] += f.y * nn;
    }
}
__device__ __forceinline__ uint2 pack4(float a, float b, float c, float d) {
    __half2 h0 = __floats2half2_rn(a, b), h1 = __floats2half2_rn(c, d);
    uint2 r; r.x = *(unsigned*)&h0; r.y = *(unsigned*)&h1; return r;
}
__device__ __forceinline__ float4 unpack4(uint2 u) {
    float2 f0 = __half22float2(*(__half2*)&u.x);
    float2 f1 = __half22float2(*(__half2*)&u.y);
    return make_float4(f0.x, f0.y, f1.x, f1.y);
}

// ---------------- stats on fp32 input x ------------------------------------------
__global__ void k_stats(const float* __restrict__ X, int N,
                        float* __restrict__ sS, float* __restrict__ sQ) {
    __shared__ float ss[HD], sq[HD];
    int t = threadIdx.x;
    if (t < HD) { ss[t] = 0.f; sq[t] = 0.f; }
    __syncthreads();
    int total  = N * HD4;
    int stride = blockDim.x * gridDim.x;
    int idx    = blockIdx.x * blockDim.x + t;
    int fb     = (idx & 31) * 4;
    float a0=0,a1=0,a2=0,a3=0,q0=0,q1=0,q2=0,q3=0;
    for (; idx < total; idx += stride) {
        float4 v = ((const float4*)X)[idx];
        a0 += v.x; q0 += v.x * v.x;
        a1 += v.y; q1 += v.y * v.y;
        a2 += v.z; q2 += v.z * v.z;
        a3 += v.w; q3 += v.w * v.w;
    }
    atomicAdd(&ss[fb+0], a0); atomicAdd(&sq[fb+0], q0);
    atomicAdd(&ss[fb+1], a1); atomicAdd(&sq[fb+1], q1);
    atomicAdd(&ss[fb+2], a2); atomicAdd(&sq[fb+2], q2);
    atomicAdd(&ss[fb+3], a3); atomicAdd(&sq[fb+3], q3);
    __syncthreads();
    if (t < HD) { atomicAdd(&sS[t], ss[t]); atomicAdd(&sQ[t], sq[t]); }
}

// ---------------- fp16 tensor-core GEMM, inline BN fold, batched, fp16 I/O -------
__global__ void __launch_bounds__(512) k_gemm_tc(GJobs jobs, int N, int doRelu,
                                                 int inHalf, float invN) {
    extern __shared__ __half sh[];
    __half* Ah = sh;
    __half* Bh = sh + 128 * AS;
    __shared__ float ssum[HD], ssq[HD], scaleSh[HD], tshSh[HD], biasSh[HD];
    __shared__ float bpart[4][HD];
    const GJob J = jobs.j[blockIdx.y];
    int t = threadIdx.x;
    if (t < HD) {
        ssum[t] = 0.f; ssq[t] = 0.f;
        float mu  = J.sSin[t] * invN;
        float var = fmaxf(J.sQin[t] * invN - mu * mu, 0.f);
        float rs  = rsqrtf(var + 1e-5f);
        scaleSh[t] = rs;
        tshSh[t]   = 1e-4f / rs - mu;
        biasSh[t]  = J.b ? J.b[t] : 0.f;
    }
    __syncthreads();
    int base = blockIdx.x * 128;
    if (inHalf) {
        const __half* Xh = (const __half*)J.X;
#pragma unroll
        for (int i = t; i < 2048; i += 512) {
            int r = i >> 4, c = i & 15, gr = base + r;
            uint4 v = make_uint4(0u, 0u, 0u, 0u);
            if (gr < N) v = ((const uint4*)Xh)[(size_t)gr * 16 + c];
            *(uint4*)&Ah[r * AS + c * 8] = v;
        }
    } else {
        const float* Xf = (const float*)J.X;
#pragma unroll
        for (int i = t; i < 4096; i += 512) {
            int r = i >> 5, c = i & 31, gr = base + r;
            float4 v = make_float4(0.f, 0.f, 0.f, 0.f);
            if (gr < N) v = ((const float4*)Xf)[(size_t)gr * 32 + c];
            __half2* dst = (__half2*)&Ah[r * AS + c * 4];
            dst[0] = __floats2half2_rn(v.x, v.y);
            dst[1] = __floats2half2_rn(v.z, v.w);
        }
    }
#pragma unroll
    for (int i = t; i < 4096; i += 512) {
        int r = i >> 5, c = i & 31;
        float4 v = ((const float4*)J.W)[i];
        float s = scaleSh[r];
        __half2* dst = (__half2*)&Bh[r * BS + c * 4];
        dst[0] = __floats2half2_rn(v.x * s, v.y * s);
        dst[1] = __floats2half2_rn(v.z * s, v.w * s);
    }
    __syncthreads();

    {
        int j = t & 127, q = t >> 7;
        float part = 0.f;
        int k0 = q * 32;
#pragma unroll
        for (int k = 0; k < 32; k++)
            part += tshSh[k0 + k] * __half2float(Bh[(k0 + k) * BS + j]);
        bpart[q][j] = part;
    }
    __syncthreads();
    if (t < HD) biasSh[t] += bpart[0][t] + bpart[1][t] + bpart[2][t] + bpart[3][t];
    __syncthreads();

    int lane = t & 31, g = lane >> 2, tg = lane & 3, w = t >> 5;
    int rwb = (w & 3) * 32;
    int cwb = (w >> 2) * 32;

    int m8 = lane >> 3, lr = lane & 7;
    int arowOff = (m8 & 1) * 8 + lr;
    int acolOff = (m8 >> 1) * 8;
    unsigned aBase = s2u(Ah);
    unsigned bBase = s2u(Bh);
    int bk = lane & 15;

    float acc[2][4][4];
#pragma unroll
    for (int m = 0; m < 2; m++)
#pragma unroll
        for (int nt = 0; nt < 4; nt++)
#pragma unroll
            for (int j = 0; j < 4; j++) acc[m][nt][j] = 0.f;

    unsigned aA[8], bA[8], aB[8], bB[8];

#define LDFRAG(K0, AA, BB)                                                      \
    {                                                                           \
        _Pragma("unroll")                                                       \
        for (int m = 0; m < 2; m++) {                                           \
            int arow = rwb + m * 16 + arowOff;                                  \
            ldsm_x4(AA + m * 4, aBase + (arow * AS + (K0) + acolOff) * 2);      \
        }                                                                       \
        _Pragma("unroll")                                                       \
        for (int nt = 0; nt < 4; nt++) {                                        \
            ldsm_x2t(BB + nt * 2, bBase + (((K0) + bk) * BS + cwb + nt * 8) * 2);\
        }                                                                       \
    }

    LDFRAG(0, aA, bA);
#pragma unroll
    for (int ks = 0; ks < 8; ks += 2) {
        if (ks + 1 < 8) LDFRAG((ks + 1) * 16, aB, bB);
#pragma unroll
        for (int m = 0; m < 2; m++)
#pragma unroll
            for (int nt = 0; nt < 4; nt++)
                mma_f16(acc[m][nt], aA + m * 4, bA + nt * 2);
        if (ks + 2 < 8) LDFRAG((ks + 2) * 16, aA, bA);
#pragma unroll
        for (int m = 0; m < 2; m++)
#pragma unroll
            for (int nt = 0; nt < 4; nt++)
                mma_f16(acc[m][nt], aB + m * 4, bB + nt * 2);
    }
#undef LDFRAG

    float ls[4][2], lq[4][2];
#pragma unroll
    for (int nt = 0; nt < 4; nt++) { ls[nt][0]=0.f; ls[nt][1]=0.f; lq[nt][0]=0.f; lq[nt][1]=0.f; }

#pragma unroll
    for (int nt = 0; nt < 4; nt++) {
        int col = cwb + nt * 8 + 2 * tg;
        float bx = biasSh[col], by = biasSh[col + 1];
#pragma unroll
        for (int m = 0; m < 2; m++) {
            int r0 = base + rwb + m * 16 + g;
            int r1 = r0 + 8;
            float y00 = acc[m][nt][0] + bx, y01 = acc[m][nt][1] + by;
            float y10 = acc[m][nt][2] + bx, y11 = acc[m][nt][3] + by;
            if (doRelu) {
                y00 = fmaxf(y00, 0.f); y01 = fmaxf(y01, 0.f);
                y10 = fmaxf(y10, 0.f); y11 = fmaxf(y11, 0.f);
            }
            if (r0 < N) {
                ((__half2*)J.Y)[(size_t)r0 * 64 + (col >> 1)] = __floats2half2_rn(y00, y01);
                ls[nt][0] += y00; lq[nt][0] += y00 * y00;
                ls[nt][1] += y01; lq[nt][1] += y01 * y01;
            }
            if (r1 < N) {
                ((__half2*)J.Y)[(size_t)r1 * 64 + (col >> 1)] = __floats2half2_rn(y10, y11);
                ls[nt][0] += y10; lq[nt][0] += y10 * y10;
                ls[nt][1] += y11; lq[nt][1] += y11 * y11;
            }
        }
    }

    if (J.sSout) {
#pragma unroll
        for (int off = 4; off <= 16; off <<= 1)
#pragma unroll
            for (int nt = 0; nt < 4; nt++)
#pragma unroll
                for (int j = 0; j < 2; j++) {
                    ls[nt][j] += __shfl_xor_sync(0xffffffffu, ls[nt][j], off);
                    lq[nt][j] += __shfl_xor_sync(0xffffffffu, lq[nt][j], off);
                }
        if (g == 0) {
#pragma unroll
            for (int nt = 0; nt < 4; nt++)
#pragma unroll
                for (int j = 0; j < 2; j++) {
                    int col = cwb + nt * 8 + 2 * tg + j;
                    atomicAdd(&ssum[col], ls[nt][j]);
                    atomicAdd(&ssq[col],  lq[nt][j]);
                }
        }
        __syncthreads();
        if (t < HD) { atomicAdd(&J.sSout[t], ssum[t]); atomicAdd(&J.sQout[t], ssq[t]); }
    }
}

// ---------------- CSR build ------------------------------------------------------
__global__ void k_hist(const int* __restrict__ row, const int* __restrict__ col, int E) {
    int e = blockIdx.x * blockDim.x + threadIdx.x;
    if (e < E) {
        atomicAdd(&g_cnt2[col[e]], 1);
        atomicAdd(&g_cnt2[MAXN + row[e]], 1);
    }
}

__global__ void __launch_bounds__(1024) k_scan1(int N) {
    __shared__ int wsum[32];
    int t = threadIdx.x;
    int idx = blockIdx.x * 1024 + t;
    int v = (idx < N) ? g_cnt2[idx] : 0;
    int x = v;
#pragma unroll
    for (int off = 1; off < 32; off <<= 1) {
        int y = __shfl_up_sync(0xffffffffu, x, off);
        if ((t & 31) >= off) x += y;
    }
    if ((t & 31) == 31) wsum[t >> 5] = x;
    __syncthreads();
    if (t < 32) {
        int y = wsum[t];
#pragma unroll
        for (int off = 1; off < 32; off <<= 1) {
            int z = __shfl_up_sync(0xffffffffu, y, off);
            if (t >= off) y += z;
        }
        wsum[t] = y;
    }
    __syncthreads();
    int winc = (t >= 32) ? wsum[(t >> 5) - 1] : 0;
    int incl = x + winc;
    if (idx < N) g_rowptr[idx] = incl - v;
    if (t == 1023) g_bsum[blockIdx.x] = incl;
}

// scan finalize + degree init + SELF-ZERO g_cnt2 for the next graph replay
__global__ void __launch_bounds__(1024) k_scanfin(int N, int nb) {
    __shared__ int s[64];
    int t = threadIdx.x;
    if (t < 64) s[t] = (t < nb) ? g_bsum[t] : 0;
    __syncthreads();
    for (int off = 1; off < 64; off <<= 1) {
        int a = (t < 64 && t >= off) ? s[t - off] : 0;
        __syncthreads();
        if (t < 64) s[t] += a;
        __syncthreads();
    }
    int boff = s[blockIdx.x] - g_bsum[blockIdx.x];
    int idx = blockIdx.x * 1024 + t;
    if (idx < N) {
        int r = g_rowptr[idx] + boff;
        g_rowptr[idx] = r;
        g_cursor[idx] = r;
        g_degu[idx] = rsqrtf((float)g_cnt2[MAXN + idx] + 1.f);
        g_degc[idx] = 1.f;
        g_dego[idx] = 1.f;
        g_cnt2[idx] = 0;            // consumed by scan1 — reset for next replay
        g_cnt2[MAXN + idx] = 0;     // consumed just above — reset for next replay
    }
    if (blockIdx.x == 0 && t == 0) g_rowptr[N] = s[63];
}

__global__ void k_fillcsr(const int* __restrict__ row, const int* __restrict__ col, int E) {
    int e = blockIdx.x * blockDim.x + threadIdx.x;
    if (e >= E) return;
    int c = col[e];
    int p = atomicAdd(&g_cursor[c], 1);
    g_er[p] = row[e];
}

// ---------------- CSR gathers (fp16 I/O), half-warp pairing, rowptr pipelined ---
__global__ void __launch_bounds__(256) k_gather(const __half* __restrict__ lin,
                                                __half* __restrict__ out,
                                                const float* __restrict__ dinv,
                                                const float* __restrict__ b, int N,
                                                float* __restrict__ sS,
                                                float* __restrict__ sQ) {
    __shared__ float ssum[HD], ssq[HD];
    int t = threadIdx.x;
    if (t < HD) { ssum[t] = 0.f; ssq[t] = 0.f; }
    __syncthreads();
    int lane = t & 31, hw = lane >> 4, hl = lane & 15;
    int warpId = (blockIdx.x * blockDim.x + t) >> 5;
    int nW = (blockDim.x * gridDim.x) >> 5;
    float4 bb0 = ((const float4*)b)[hl * 2 + 0];
    float4 bb1 = ((const float4*)b)[hl * 2 + 1];
    float st[8] = {0,0,0,0,0,0,0,0}, qt[8] = {0,0,0,0,0,0,0,0};
    int pstart = 0, pend = 0;
    if (warpId < N) { pstart = g_rowptr[warpId]; pend = g_rowptr[warpId + 1]; }
    for (int i = warpId; i < N; i += nW) {
        int start = pstart, end = pend;
        int inxt = i + nW;
        if (inxt < N) { pstart = g_rowptr[inxt]; pend = g_rowptr[inxt + 1]; }
        float di = dinv[i];
        float a[8] = {0,0,0,0,0,0,0,0};
        if (hw == 0) {
            uint4 u = __ldg((const uint4*)(lin + (size_t)i * HD) + hl);
            fma8(a, u, di * di);
        }
        int j0 = start;
        for (; j0 + 32 <= end; j0 += 32) {
            int r = g_er[j0 + lane];
            float dr = dinv[r];
#pragma unroll
            for (int k = 0; k < 16; k++) {
                int src = 2 * k + hw;
                int   rr = __shfl_sync(0xffffffffu, r, src);
                float nn = __shfl_sync(0xffffffffu, dr, src) * di;
                uint4 u = __ldg((const uint4*)(lin + (size_t)rr * HD) + hl);
                fma8(a, u, nn);
            }
        }
        if (j0 < end) {
            int cnt = end - j0;
            int r = 0; float dr = 0.f;
            if (lane < cnt) { r = g_er[j0 + lane]; dr = dinv[r]; }
            int pairs = (cnt + 1) >> 1;
            for (int k = 0; k < pairs; k++) {
                int src = 2 * k + hw;
                int   rr = __shfl_sync(0xffffffffu, r, src);
                float nn = __shfl_sync(0xffffffffu, dr, src) * di;
                if (src < cnt) {
                    uint4 u = __ldg((const uint4*)(lin + (size_t)rr * HD) + hl);
                    fma8(a, u, nn);
                }
            }
        }
#pragma unroll
        for (int j = 0; j < 8; j++)
            a[j] += __shfl_xor_sync(0xffffffffu, a[j], 16);
        if (hw == 0) {
            a[0] = fmaxf(a[0] + bb0.x, 0.f); a[1] = fmaxf(a[1] + bb0.y, 0.f);
            a[2] = fmaxf(a[2] + bb0.z, 0.f); a[3] = fmaxf(a[3] + bb0.w, 0.f);
            a[4] = fmaxf(a[4] + bb1.x, 0.f); a[5] = fmaxf(a[5] + bb1.y, 0.f);
            a[6] = fmaxf(a[6] + bb1.z, 0.f); a[7] = fmaxf(a[7] + bb1.w, 0.f);
            uint2 p0 = pack4(a[0], a[1], a[2], a[3]);
            uint2 p1 = pack4(a[4], a[5], a[6], a[7]);
            ((uint4*)(out + (size_t)i * HD))[hl] = make_uint4(p0.x, p0.y, p1.x, p1.y);
#pragma unroll
            for (int j = 0; j < 8; j++) { st[j] += a[j]; qt[j] += a[j] * a[j]; }
        }
    }
    if (sS) {
        if (hw == 0) {
#pragma unroll
            for (int j = 0; j < 8; j++) {
                atomicAdd(&ssum[hl * 8 + j], st[j]);
                atomicAdd(&ssq[hl * 8 + j],  qt[j]);
            }
        }
        __syncthreads();
        if (t < HD) { atomicAdd(&sS[t], ssum[t]); atomicAdd(&sQ[t], ssq[t]); }
    }
}

// weighted ctx/obj gather with inline edge softmax from g_ed, rowptr pipelined
__global__ void __launch_bounds__(256) k_gather2(const __half* __restrict__ linC,
                                                 const __half* __restrict__ linO,
                                                 __half* __restrict__ outC,
                                                 __half* __restrict__ outO,
                                                 const float* __restrict__ dc,
                                                 const float* __restrict__ dd,
                                                 const float* __restrict__ bc,
                                                 const float* __restrict__ bo,
                                                 const float* __restrict__ bea, int N,
                                                 float* sSc, float* sQc,
                                                 float* sSo, float* sQo) {
    __shared__ float red[4][HD];
    int t = threadIdx.x;
    for (int i = t; i < 4 * HD; i += blockDim.x) ((float*)red)[i] = 0.f;
    __syncthreads();
    int lane = t & 31, hw = lane >> 4, hl = lane & 15;
    int warpId = (blockIdx.x * blockDim.x + t) >> 5;
    int nW = (blockDim.x * gridDim.x) >> 5;
    float bead = bea[1] - bea[0];
    float4 bc0 = ((const float4*)bc)[hl * 2 + 0];
    float4 bc1 = ((const float4*)bc)[hl * 2 + 1];
    float4 bo0 = ((const float4*)bo)[hl * 2 + 0];
    float4 bo1 = ((const float4*)bo)[hl * 2 + 1];
    float stc[8] = {0,0,0,0,0,0,0,0}, qtc[8] = {0,0,0,0,0,0,0,0};
    float sto[8] = {0,0,0,0,0,0,0,0}, qto[8] = {0,0,0,0,0,0,0,0};
    int pstart = 0, pend = 0;
    if (warpId < N) { pstart = g_rowptr[warpId]; pend = g_rowptr[warpId + 1]; }
    for (int i = warpId; i < N; i += nW) {
        int start = pstart, end = pend;
        int inxt = i + nW;
        if (inxt < N) { pstart = g_rowptr[inxt]; pend = g_rowptr[inxt + 1]; }
        float dci = rsqrtf(dc[i]), doi = rsqrtf(dd[i]);
        float edyi = g_ed[i].y + bead;
        float aC[8] = {0,0,0,0,0,0,0,0}, aO[8] = {0,0,0,0,0,0,0,0};
        if (hw == 0) {
            uint4 u = __ldg((const uint4*)(linC + (size_t)i * HD) + hl);
            fma8(aC, u, dci * dci);
        } else {
            uint4 u = __ldg((const uint4*)(linO + (size_t)i * HD) + hl);
            fma8(aO, u, doi * doi);
        }
        int j0 = start;
        for (; j0 + 32 <= end; j0 += 32) {
            int r = g_er[j0 + lane];
            float2 ed = __ldg(&g_ed[r]);
            float delta = edyi + ed.x;
            float s1 = 1.f / (1.f + expf(-delta));
            float s0 = 1.f - s1;
            float wc = rsqrtf(dc[r]) * s0;
            float wo = rsqrtf(dd[r]) * s1;
#pragma unroll
            for (int k = 0; k < 16; k++) {
                int src = 2 * k + hw;
                int   rr = __shfl_sync(0xffffffffu, r, src);
                float nc = __shfl_sync(0xffffffffu, wc, src) * dci;
                float no = __shfl_sync(0xffffffffu, wo, src) * doi;
                uint4 uC = __ldg((const uint4*)(linC + (size_t)rr * HD) + hl);
                uint4 uO = __ldg((const uint4*)(linO + (size_t)rr * HD) + hl);
                fma8(aC, uC, nc);
                fma8(aO, uO, no);
            }
        }
        if (j0 < end) {
            int cnt = end - j0;
            int r = 0; float wc = 0.f, wo = 0.f;
            if (lane < cnt) {
                r = g_er[j0 + lane];
                float2 ed = __ldg(&g_ed[r]);
                float delta = edyi + ed.x;
                float s1 = 1.f / (1.f + expf(-delta));
                float s0 = 1.f - s1;
                wc = rsqrtf(dc[r]) * s0;
                wo = rsqrtf(dd[r]) * s1;
            }
            int pairs = (cnt + 1) >> 1;
            for (int k = 0; k < pairs; k++) {
                int src = 2 * k + hw;
                int   rr = __shfl_sync(0xffffffffu, r, src);
                float nc = __shfl_sync(0xffffffffu, wc, src) * dci;
                float no = __shfl_sync(0xffffffffu, wo, src) * doi;
                if (src < cnt) {
                    uint4 uC = __ldg((const uint4*)(linC + (size_t)rr * HD) + hl);
                    uint4 uO = __ldg((const uint4*)(linO + (size_t)rr * HD) + hl);
                    fma8(aC, uC, nc);
                    fma8(aO, uO, no);
                }
            }
        }
#pragma unroll
        for (int j = 0; j < 8; j++) {
            aC[j] += __shfl_xor_sync(0xffffffffu, aC[j], 16);
            aO[j] += __shfl_xor_sync(0xffffffffu, aO[j], 16);
        }
        if (hw == 0) {
            aC[0] = fmaxf(aC[0] + bc0.x, 0.f); aC[1] = fmaxf(aC[1] + bc0.y, 0.f);
            aC[2] = fmaxf(aC[2] + bc0.z, 0.f); aC[3] = fmaxf(aC[3] + bc0.w, 0.f);
            aC[4] = fmaxf(aC[4] + bc1.x, 0.f); aC[5] = fmaxf(aC[5] + bc1.y, 0.f);
            aC[6] = fmaxf(aC[6] + bc1.z, 0.f); aC[7] = fmaxf(aC[7] + bc1.w, 0.f);
            aO[0] = fmaxf(aO[0] + bo0.x, 0.f); aO[1] = fmaxf(aO[1] + bo0.y, 0.f);
            aO[2] = fmaxf(aO[2] + bo0.z, 0.f); aO[3] = fmaxf(aO[3] + bo0.w, 0.f);
            aO[4] = fmaxf(aO[4] + bo1.x, 0.f); aO[5] = fmaxf(aO[5] + bo1.y, 0.f);
            aO[6] = fmaxf(aO[6] + bo1.z, 0.f); aO[7] = fmaxf(aO[7] + bo1.w, 0.f);
            uint2 c0 = pack4(aC[0], aC[1], aC[2], aC[3]);
            uint2 c1 = pack4(aC[4], aC[5], aC[6], aC[7]);
            uint2 o0 = pack4(aO[0], aO[1], aO[2], aO[3]);
            uint2 o1 = pack4(aO[4], aO[5], aO[6], aO[7]);
            ((uint4*)(outC + (size_t)i * HD))[hl] = make_uint4(c0.x, c0.y, c1.x, c1.y);
            ((uint4*)(outO + (size_t)i * HD))[hl] = make_uint4(o0.x, o0.y, o1.x, o1.y);
#pragma unroll
            for (int j = 0; j < 8; j++) {
                stc[j] += aC[j]; qtc[j] += aC[j] * aC[j];
                sto[j] += aO[j]; qto[j] += aO[j] * aO[j];
            }
        }
    }
    if (hw == 0) {
#pragma unroll
        for (int j = 0; j < 8; j++) {
            atomicAdd(&red[0][hl * 8 + j], stc[j]);
            atomicAdd(&red[1][hl * 8 + j], qtc[j]);
            atomicAdd(&red[2][hl * 8 + j], sto[j]);
            atomicAdd(&red[3][hl * 8 + j], qto[j]);
        }
    }
    __syncthreads();
    if (t < HD) {
        atomicAdd(&sSc[t], red[0][t]); atomicAdd(&sQc[t], red[1][t]);
        atomicAdd(&sSo[t], red[2][t]); atomicAdd(&sQo[t], red[3][t]);
    }
}

// ---------------- attention node pass ---------------------------------------------
__global__ void k_att_node(const __half* __restrict__ h,
                           const float* __restrict__ Wna, const float* __restrict__ bna,
                           const float* __restrict__ Wea,
                           __half* __restrict__ xc, __half* __restrict__ xo, int N,
                           float* sSc, float* sQc, float* sSo, float* sQo) {
    __shared__ float Wc[HD * 6];
    __shared__ float red[4][HD];
    int t = threadIdx.x;
    for (int i = t; i < HD * 6; i += blockDim.x) {
        int k = i / 6, j = i % 6;
        float v;
        if (j < 2)      v = Wna[k * 2 + j];
        else if (j < 4) v = Wea[k * 2 + (j - 2)];
        else            v = Wea[(HD + k) * 2 + (j - 4)];
        Wc[i] = v;
    }
    for (int i = t; i < 4 * HD; i += blockDim.x) ((float*)red)[i] = 0.f;
    __syncthreads();
    int warps = (blockDim.x * gridDim.x) >> 5;
    int gw = (blockIdx.x * blockDim.x + t) >> 5;
    int l  = t & 31;
    float b0 = bna[0], b1 = bna[1];
    float sc[4]={0,0,0,0}, qc[4]={0,0,0,0}, so[4]={0,0,0,0}, qo[4]={0,0,0,0};
    for (int i = gw; i < N; i += warps) {
        float4 hv = unpack4(((const uint2*)(h + (size_t)i * HD))[l]);
        float p[6];
#pragma unroll
        for (int j = 0; j < 6; j++) {
            p[j] = hv.x * Wc[(4*l+0)*6 + j] + hv.y * Wc[(4*l+1)*6 + j]
                 + hv.z * Wc[(4*l+2)*6 + j] + hv.w * Wc[(4*l+3)*6 + j];
        }
#pragma unroll
        for (int off = 16; off; off >>= 1)
#pragma unroll
            for (int j = 0; j < 6; j++)
                p[j] += __shfl_xor_sync(0xffffffffu, p[j], off);
        float l0 = p[0] + b0, l1 = p[1] + b1;
        float m  = fmaxf(l0, l1);
        float e0 = expf(l0 - m), e1 = expf(l1 - m);
        float inv = 1.f / (e0 + e1);
        float a0 = e0 * inv, a1 = e1 * inv;
        float4 vc = make_float4(hv.x*a0, hv.y*a0, hv.z*a0, hv.w*a0);
        float4 vo = make_float4(hv.x*a1, hv.y*a1, hv.z*a1, hv.w*a1);
        ((uint2*)(xc + (size_t)i * HD))[l] = pack4(vc.x, vc.y, vc.z, vc.w);
        ((uint2*)(xo + (size_t)i * HD))[l] = pack4(vo.x, vo.y, vo.z, vo.w);
        sc[0]+=vc.x; qc[0]+=vc.x*vc.x; sc[1]+=vc.y; qc[1]+=vc.y*vc.y;
        sc[2]+=vc.z; qc[2]+=vc.z*vc.z; sc[3]+=vc.w; qc[3]+=vc.w*vc.w;
        so[0]+=vo.x; qo[0]+=vo.x*vo.x; so[1]+=vo.y; qo[1]+=vo.y*vo.y;
        so[2]+=vo.z; qo[2]+=vo.z*vo.z; so[3]+=vo.w; qo[3]+=vo.w*vo.w;
        if (l == 0) g_ed[i] = make_float2(p[3] - p[2], p[5] - p[4]);
    }
#pragma unroll
    for (int j = 0; j < 4; j++) {
        atomicAdd(&red[0][l*4+j], sc[j]);
        atomicAdd(&red[1][l*4+j], qc[j]);
        atomicAdd(&red[2][l*4+j], so[j]);
        atomicAdd(&red[3][l*4+j], qo[j]);
    }
    __syncthreads();
    if (t < HD) {
        atomicAdd(&sSc[t], red[0][t]); atomicAdd(&sQc[t], red[1][t]);
        atomicAdd(&sSo[t], red[2][t]); atomicAdd(&sQo[t], red[3][t]);
    }
}

__global__ void k_att_edge(const int* __restrict__ row, const int* __restrict__ col,
                           const float* __restrict__ bea, int E) {
    int e = blockIdx.x * blockDim.x + threadIdx.x;
    if (e >= E) return;
    int r = row[e], c = col[e];
    float delta = (bea[1] - bea[0]) + g_ed[r].x + g_ed[c].y;
    float a1 = 1.f / (1.f + expf(-delta));
    float a0 = 1.f - a1;
    atomicAdd(&g_degc[r], a0);
    atomicAdd(&g_dego[r], a1);
}

__global__ void k_permadd_stats(const __half* __restrict__ xc, const __half* __restrict__ xo,
                                const int* __restrict__ perm, __half* __restrict__ z, int N,
                                float* __restrict__ sS, float* __restrict__ sQ) {
    __shared__ float ssum[HD], ssq[HD];
    int t = threadIdx.x;
    if (t < HD) { ssum[t] = 0.f; ssq[t] = 0.f; }
    __syncthreads();
    int total  = N * HD4;
    int stride = blockDim.x * gridDim.x;
    int idx    = blockIdx.x * blockDim.x + t;
    int fb     = (idx & 31) * 4;
    float a0=0,a1=0,a2=0,a3=0,q0=0,q1=0,q2=0,q3=0;
    for (; idx < total; idx += stride) {
        int i = idx >> 5, l = idx & 31;
        int p = perm[i];
        float4 a = unpack4(((const uint2*)(xc + (size_t)p * HD))[l]);
        float4 b = unpack4(((const uint2*)xo)[idx]);
        a.x += b.x; a.y += b.y; a.z += b.z; a.w += b.w;
        ((uint2*)z)[idx] = pack4(a.x, a.y, a.z, a.w);
        a0 += a.x; q0 += a.x*a.x; a1 += a.y; q1 += a.y*a.y;
        a2 += a.z; q2 += a.z*a.z; a3 += a.w; q3 += a.w*a.w;
    }
    atomicAdd(&ssum[fb+0], a0); atomicAdd(&ssq[fb+0], q0);
    atomicAdd(&ssum[fb+1], a1); atomicAdd(&ssq[fb+1], q1);
    atomicAdd(&ssum[fb+2], a2); atomicAdd(&ssq[fb+2], q2);
    atomicAdd(&ssum[fb+3], a3); atomicAdd(&ssq[fb+3], q3);
    __syncthreads();
    if (t < HD) { atomicAdd(&sS[t], ssum[t]); atomicAdd(&sQ[t], ssq[t]); }
}

// ---------------- [N,128]x[128,10] + log_softmax (fp16 Z), batched --------------
__global__ void k_gemm2_lsm(LJobs jobs, int N, float invN) {
    __shared__ float Ws[HD * 10];
    __shared__ float bs[10];
    __shared__ float scaleSh[HD], tshSh[HD];
    const LJob J = jobs.j[blockIdx.y];
    int t = threadIdx.x;
    if (t < HD) {
        float mu  = J.sSin[t] * invN;
        float var = fmaxf(J.sQin[t] * invN - mu * mu, 0.f);
        float rs  = rsqrtf(var + 1e-5f);
        scaleSh[t] = rs;
        tshSh[t]   = 1e-4f / rs - mu;
    }
    __syncthreads();
    for (int i = t; i < HD * 10; i += blockDim.x)
        Ws[i] = scaleSh[i / 10] * J.W[i];
    __syncthreads();
    if (t < 160) {
        int j = t / 16, seg = t % 16;
        float part = 0.f;
#pragma unroll
        for (int k = 0; k < 8; k++) {
            int kk = seg * 8 + k;
            part += tshSh[kk] * Ws[kk * 10 + j];
        }
#pragma unroll
        for (int off = 8; off; off >>= 1)
            part += __shfl_down_sync(0xffffffffu, part, off, 16);
        if (seg == 0) bs[j] = J.b[j] + part;
    }
    __syncthreads();
    int warps = (blockDim.x * gridDim.x) >> 5;
    int gw = (blockIdx.x * blockDim.x + t) >> 5;
    int l  = t & 31;
    for (int i = gw; i < N; i += warps) {
        float4 z = unpack4(((const uint2*)(J.Z + (size_t)i * HD))[l]);
        float p[10];
#pragma unroll
        for (int j = 0; j < 10; j++) {
            p[j] = z.x * Ws[(4*l+0)*10 + j] + z.y * Ws[(4*l+1)*10 + j]
                 + z.z * Ws[(4*l+2)*10 + j] + z.w * Ws[(4*l+3)*10 + j];
        }
#pragma unroll
        for (int off = 16; off; off >>= 1)
#pragma unroll
            for (int j = 0; j < 10; j++)
                p[j] += __shfl_xor_sync(0xffffffffu, p[j], off);
        float m = -1e30f;
#pragma unroll
        for (int j = 0; j < 10; j++) { p[j] += bs[j]; m = fmaxf(m, p[j]); }
        float s = 0.f;
#pragma unroll
        for (int j = 0; j < 10; j++) s += expf(p[j] - m);
        float lse = m + logf(s);
        if (l < 10) J.out[(size_t)i * 10 + l] = p[l] - lse;
    }
}

// ---------------- host orchestration ------------------------------------------------
extern "C" void kernel_launch(void* const* d_in, const int* in_sizes, int n_in,
                              void* d_out, int out_size) {
    const float* x      = (const float*)d_in[0];
    const int*   ei     = (const int*)  d_in[1];
    const int*   perm   = (const int*)  d_in[2];
    const float* W_feat = (const float*)d_in[3];
    const float* b_feat = (const float*)d_in[4];
    const float* W_convs= (const float*)d_in[5];
    const float* b_convs= (const float*)d_in[6];
    const float* W_ea   = (const float*)d_in[7];
    const float* b_ea   = (const float*)d_in[8];
    const float* W_na   = (const float*)d_in[9];
    const float* b_na   = (const float*)d_in[10];
    const float* W_ctx  = (const float*)d_in[11];
    const float* b_ctx  = (const float*)d_in[12];
    const float* W_obj  = (const float*)d_in[13];
    const float* b_obj  = (const float*)d_in[14];
    const float* W_fc1  = (const float*)d_in[15];
    const float* b_fc1  = (const float*)d_in[16];
    const float* W_fc2  = (const float*)d_in[17];
    const float* b_fc2  = (const float*)d_in[18];

    int N = in_sizes[0] / HD;
    int E = in_sizes[1] / 2;
    const int* row = ei;
    const int* col = ei + E;
    float* out = (float*)d_out;

    static cudaStream_t sB = nullptr;
    static cudaEvent_t ev0, evCSR, ev1, evAE;
    if (!sB) {
        cudaStreamCreateWithFlags(&sB, cudaStreamNonBlocking);
        cudaEventCreateWithFlags(&ev0,   cudaEventDisableTiming);
        cudaEventCreateWithFlags(&evCSR, cudaEventDisableTiming);
        cudaEventCreateWithFlags(&ev1,   cudaEventDisableTiming);
        cudaEventCreateWithFlags(&evAE,  cudaEventDisableTiming);
    }

    float* Bbase = nullptr;
    cudaGetSymbolAddress((void**)&Bbase, g_B);
    __half* H0 = (__half*)(Bbase + 0 * (size_t)MAXN * HD);
    __half* H1 = (__half*)(Bbase + 1 * (size_t)MAXN * HD);
    __half* H2 = (__half*)(Bbase + 2 * (size_t)MAXN * HD);
    __half* H3 = (__half*)(Bbase + 3 * (size_t)MAXN * HD);
    __half* H4 = (__half*)(Bbase + 4 * (size_t)MAXN * HD);
    __half* H5 = (__half*)(Bbase + 5 * (size_t)MAXN * HD);
    float *degup, *degcp, *degop, *statsp;
    cudaGetSymbolAddress((void**)&degup,  g_degu);
    cudaGetSymbolAddress((void**)&degcp,  g_degc);
    cudaGetSymbolAddress((void**)&degop,  g_dego);
    cudaGetSymbolAddress((void**)&statsp, g_stats);
    auto S = [&](int i) { return statsp + i * HD; };
    auto Q = [&](int i) { return statsp + (NSLOT + i) * HD; };

    const int gemm_smem = 2 * 128 * AS * (int)sizeof(__half);
    cudaFuncSetAttribute(k_gemm_tc, cudaFuncAttributeMaxDynamicSharedMemorySize, gemm_smem);

    int gbGemm = (N + 127) / 128;
    int gbE    = (E + 255) / 256;
    int nb     = (N + 1023) / 1024;
    float invN = 1.f / (float)N;

    auto gemm1 = [&](const void* X, __half* Y, const float* W, const float* b,
                     int sin, int sout, int relu, int inHalf) {
        GJobs js{};
        js.j[0] = {X, Y, W, b, S(sin), Q(sin),
                   sout >= 0 ? S(sout) : nullptr, sout >= 0 ? Q(sout) : nullptr};
        k_gemm_tc<<<dim3(gbGemm, 1), 512, gemm_smem>>>(js, N, relu, inHalf, invN);
    };

    // ---- fork: CSR build on side stream (cnt2 pre-zeroed by prior replay) ----
    cudaEventRecord(ev0, 0);
    cudaStreamWaitEvent(sB, ev0, 0);
    k_hist<<<gbE, 256, 0, sB>>>(row, col, E);
    k_scan1<<<nb, 1024, 0, sB>>>(N);
    k_scanfin<<<nb, 1024, 0, sB>>>(N, nb);
    k_fillcsr<<<gbE, 256, 0, sB>>>(row, col, E);
    cudaEventRecord(evCSR, sB);

    // main
    cudaMemsetAsync(statsp, 0, 2 * NSLOT * HD * sizeof(float), 0);
    k_stats<<<512, 256>>>(x, N, S(0), Q(0));
    gemm1(x, H2, W_feat, b_feat, 0, 1, 1, 0);
    gemm1(H2, H1, W_convs + 0 * HD * HD, nullptr, 1, -1, 0, 1);

    cudaStreamWaitEvent(0, evCSR, 0);
    k_gather<<<1024, 256>>>(H1, H0, degup, b_convs + 0 * HD, N, S(2), Q(2));
    gemm1(H0, H1, W_convs + 1 * HD * HD, nullptr, 2, -1, 0, 1);
    k_gather<<<1024, 256>>>(H1, H2, degup, b_convs + 1 * HD, N, S(3), Q(3));
    gemm1(H2, H1, W_convs + 2 * HD * HD, nullptr, 3, -1, 0, 1);
    k_gather<<<1024, 256>>>(H1, H0, degup, b_convs + 2 * HD, N, nullptr, nullptr);

    // attention node projections
    k_att_node<<<256, 256>>>(H0, W_na, b_na, W_ea, H2, H3, N, S(4), Q(4), S(5), Q(5));

    // fork: att-weighted degree sums on side stream
    cudaEventRecord(ev1, 0);
    cudaStreamWaitEvent(sB, ev1, 0);
    k_att_edge<<<gbE, 256, 0, sB>>>(row, col, b_ea, E);
    cudaEventRecord(evAE, sB);

    {
        GJobs js{};
        js.j[0] = {H2, H1, W_ctx, nullptr, S(4), Q(4), nullptr, nullptr};
        js.j[1] = {H3, H5, W_obj, nullptr, S(5), Q(5), nullptr, nullptr};
        k_gemm_tc<<<dim3(gbGemm, 2), 512, gemm_smem>>>(js, N, 0, 1, invN);
    }
    cudaStreamWaitEvent(0, evAE, 0);
    k_gather2<<<1024, 256>>>(H1, H5, H4, H3, degcp, degop, b_ctx, b_obj, b_ea, N,
                             S(6), Q(6), S(7), Q(7));

    k_permadd_stats<<<256, 256>>>(H4, H3, perm, H1, N, S(11), Q(11));

    {
        GJobs js{};
        js.j[0] = {H4, H0, W_fc1 + 0 * HD * HD, b_fc1 + 0 * HD, S(6),  Q(6),  S(8),  Q(8)};
        js.j[1] = {H3, H5, W_fc1 + 1 * HD * HD, b_fc1 + 1 * HD, S(7),  Q(7),  S(9),  Q(9)};
        js.j[2] = {H1, H2, W_fc1 + 2 * HD * HD, b_fc1 + 2 * HD, S(11), Q(11), S(10), Q(10)};
        k_gemm_tc<<<dim3(gbGemm, 3), 512, gemm_smem>>>(js, N, 1, 1, invN);
    }
    {
        LJobs js{};
        js.j[0] = {H0, out,                      W_fc2 + 0 * HD * 10, b_fc2 + 0 * 10, S(8),  Q(8)};
        js.j[1] = {H5, out + (size_t)N * 10,     W_fc2 + 1 * HD * 10, b_fc2 + 1 * 10, S(9),  Q(9)};
        js.j[2] = {H2, out + (size_t)2 * N * 10, W_fc2 + 2 * HD * 10, b_fc2 + 2 * 10, S(10), Q(10)};
        k_gemm2_lsm<<<dim3(512, 3), 256>>>(js, N, invN);
    }
}

// round 16
// speedup vs baseline: 1.0460x; 1.0460x over previous
#include <cuda_runtime.h>
#include <cuda_fp16.h>

#define HD   128
#define HD4  32
#define MAXN 50000
#define MAXE 800000
#define AS   136
#define BS   136
#define NSLOT 12

// ---------------- scratch ------------------------------------------------------
static __device__ float  g_B[6][(size_t)MAXN * HD];
static __device__ float2 g_ed[MAXN];
static __device__ float  g_degu[MAXN];
static __device__ float  g_degc[MAXN];
static __device__ float  g_dego[MAXN];
static __device__ float  g_stats[2 * NSLOT * HD];
// CSR (g_cnt2 is self-zeroing: scanfin clears it for the next graph replay)
static __device__ int    g_cnt2[2 * MAXN];
static __device__ int    g_rowptr[MAXN + 1];
static __device__ int    g_cursor[MAXN];
static __device__ int    g_er[MAXE];
static __device__ int    g_bsum[64];

struct GJob {
    const void* X; __half* Y; const float* W; const float* b;
    const float* sSin; const float* sQin; float* sSout; float* sQout;
};
struct GJobs { GJob j[3]; };
struct LJob {
    const __half* Z; float* out; const float* W; const float* b;
    const float* sSin; const float* sQin;
};
struct LJobs { LJob j[3]; };

__device__ __forceinline__ unsigned s2u(const void* p) {
    return (unsigned)__cvta_generic_to_shared(p);
}
__device__ __forceinline__ void ldsm_x4(unsigned* a, unsigned addr) {
    asm volatile("ldmatrix.sync.aligned.m8n8.x4.shared.b16 {%0,%1,%2,%3}, [%4];"
                 : "=r"(a[0]), "=r"(a[1]), "=r"(a[2]), "=r"(a[3]) : "r"(addr));
}
__device__ __forceinline__ void ldsm_x2t(unsigned* b, unsigned addr) {
    asm volatile("ldmatrix.sync.aligned.m8n8.x2.trans.shared.b16 {%0,%1}, [%2];"
                 : "=r"(b[0]), "=r"(b[1]) : "r"(addr));
}
__device__ __forceinline__ void mma_f16(float* c, const unsigned* a, const unsigned* b) {
    asm volatile(
        "mma.sync.aligned.m16n8k16.row.col.f32.f16.f16.f32 "
        "{%0,%1,%2,%3}, {%4,%5,%6,%7}, {%8,%9}, {%0,%1,%2,%3};"
        : "+f"(c[0]), "+f"(c[1]), "+f"(c[2]), "+f"(c[3])
        : "r"(a[0]), "r"(a[1]), "r"(a[2]), "r"(a[3]), "r"(b[0]), "r"(b[1]));
}
__device__ __forceinline__ void fma8(float* a, uint4 u, float nn) {
    __half2* h = (__half2*)&u;
#pragma unroll
    for (int j = 0; j < 4; j++) {
        float2 f = __half22float2(h[j]);
        a[2*j]   += f.x * nn;
        a[2*j+1] += f.y * nn;
    }
}
__device__ __forceinline__ uint2 pack4(float a, float b, float c, float d) {
    __half2 h0 = __floats2half2_rn(a, b), h1 = __floats2half2_rn(c, d);
    uint2 r; r.x = *(unsigned*)&h0; r.y = *(unsigned*)&h1; return r;
}
__device__ __forceinline__ float4 unpack4(uint2 u) {
    float2 f0 = __half22float2(*(__half2*)&u.x);
    float2 f1 = __half22float2(*(__half2*)&u.y);
    return make_float4(f0.x, f0.y, f1.x, f1.y);
}

// ---------------- stats on fp32 input x ------------------------------------------
__global__ void k_stats(const float* __restrict__ X, int N,
                        float* __restrict__ sS, float* __restrict__ sQ) {
    __shared__ float ss[HD], sq[HD];
    int t = threadIdx.x;
    if (t < HD) { ss[t] = 0.f; sq[t] = 0.f; }
    __syncthreads();
    int total  = N * HD4;
    int stride = blockDim.x * gridDim.x;
    int idx    = blockIdx.x * blockDim.x + t;
    int fb     = (idx & 31) * 4;
    float a0=0,a1=0,a2=0,a3=0,q0=0,q1=0,q2=0,q3=0;
    for (; idx < total; idx += stride) {
        float4 v = ((const float4*)X)[idx];
        a0 += v.x; q0 += v.x * v.x;
        a1 += v.y; q1 += v.y * v.y;
        a2 += v.z; q2 += v.z * v.z;
        a3 += v.w; q3 += v.w * v.w;
    }
    atomicAdd(&ss[fb+0], a0); atomicAdd(&sq[fb+0], q0);
    atomicAdd(&ss[fb+1], a1); atomicAdd(&sq[fb+1], q1);
    atomicAdd(&ss[fb+2], a2); atomicAdd(&sq[fb+2], q2);
    atomicAdd(&ss[fb+3], a3); atomicAdd(&sq[fb+3], q3);
    __syncthreads();
    if (t < HD) { atomicAdd(&sS[t], ss[t]); atomicAdd(&sQ[t], sq[t]); }
}

// ---------------- fp16 tensor-core GEMM, inline BN fold, batched, fp16 I/O -------
__global__ void __launch_bounds__(512) k_gemm_tc(GJobs jobs, int N, int doRelu,
                                                 int inHalf, float invN) {
    extern __shared__ __half sh[];
    __half* Ah = sh;
    __half* Bh = sh + 128 * AS;
    __shared__ float ssum[HD], ssq[HD], scaleSh[HD], tshSh[HD], biasSh[HD];
    __shared__ float bpart[4][HD];
    const GJob J = jobs.j[blockIdx.y];
    int t = threadIdx.x;
    if (t < HD) {
        ssum[t] = 0.f; ssq[t] = 0.f;
        float mu  = J.sSin[t] * invN;
        float var = fmaxf(J.sQin[t] * invN - mu * mu, 0.f);
        float rs  = rsqrtf(var + 1e-5f);
        scaleSh[t] = rs;
        tshSh[t]   = 1e-4f / rs - mu;
        biasSh[t]  = J.b ? J.b[t] : 0.f;
    }
    __syncthreads();
    int base = blockIdx.x * 128;
    if (inHalf) {
        const __half* Xh = (const __half*)J.X;
#pragma unroll
        for (int i = t; i < 2048; i += 512) {
            int r = i >> 4, c = i & 15, gr = base + r;
            uint4 v = make_uint4(0u, 0u, 0u, 0u);
            if (gr < N) v = ((const uint4*)Xh)[(size_t)gr * 16 + c];
            *(uint4*)&Ah[r * AS + c * 8] = v;
        }
    } else {
        const float* Xf = (const float*)J.X;
#pragma unroll
        for (int i = t; i < 4096; i += 512) {
            int r = i >> 5, c = i & 31, gr = base + r;
            float4 v = make_float4(0.f, 0.f, 0.f, 0.f);
            if (gr < N) v = ((const float4*)Xf)[(size_t)gr * 32 + c];
            __half2* dst = (__half2*)&Ah[r * AS + c * 4];
            dst[0] = __floats2half2_rn(v.x, v.y);
            dst[1] = __floats2half2_rn(v.z, v.w);
        }
    }
#pragma unroll
    for (int i = t; i < 4096; i += 512) {
        int r = i >> 5, c = i & 31;
        float4 v = ((const float4*)J.W)[i];
        float s = scaleSh[r];
        __half2* dst = (__half2*)&Bh[r * BS + c * 4];
        dst[0] = __floats2half2_rn(v.x * s, v.y * s);
        dst[1] = __floats2half2_rn(v.z * s, v.w * s);
    }
    __syncthreads();

    {
        int j = t & 127, q = t >> 7;
        float part = 0.f;
        int k0 = q * 32;
#pragma unroll
        for (int k = 0; k < 32; k++)
            part += tshSh[k0 + k] * __half2float(Bh[(k0 + k) * BS + j]);
        bpart[q][j] = part;
    }
    __syncthreads();
    if (t < HD) biasSh[t] += bpart[0][t] + bpart[1][t] + bpart[2][t] + bpart[3][t];
    __syncthreads();

    int lane = t & 31, g = lane >> 2, tg = lane & 3, w = t >> 5;
    int rwb = (w & 3) * 32;
    int cwb = (w >> 2) * 32;

    int m8 = lane >> 3, lr = lane & 7;
    int arowOff = (m8 & 1) * 8 + lr;
    int acolOff = (m8 >> 1) * 8;
    unsigned aBase = s2u(Ah);
    unsigned bBase = s2u(Bh);
    int bk = lane & 15;

    float acc[2][4][4];
#pragma unroll
    for (int m = 0; m < 2; m++)
#pragma unroll
        for (int nt = 0; nt < 4; nt++)
#pragma unroll
            for (int j = 0; j < 4; j++) acc[m][nt][j] = 0.f;

    unsigned aA[8], bA[8], aB[8], bB[8];

#define LDFRAG(K0, AA, BB)                                                      \
    {                                                                           \
        _Pragma("unroll")                                                       \
        for (int m = 0; m < 2; m++) {                                           \
            int arow = rwb + m * 16 + arowOff;                                  \
            ldsm_x4(AA + m * 4, aBase + (arow * AS + (K0) + acolOff) * 2);      \
        }                                                                       \
        _Pragma("unroll")                                                       \
        for (int nt = 0; nt < 4; nt++) {                                        \
            ldsm_x2t(BB + nt * 2, bBase + (((K0) + bk) * BS + cwb + nt * 8) * 2);\
        }                                                                       \
    }

    LDFRAG(0, aA, bA);
#pragma unroll
    for (int ks = 0; ks < 8; ks += 2) {
        if (ks + 1 < 8) LDFRAG((ks + 1) * 16, aB, bB);
#pragma unroll
        for (int m = 0; m < 2; m++)
#pragma unroll
            for (int nt = 0; nt < 4; nt++)
                mma_f16(acc[m][nt], aA + m * 4, bA + nt * 2);
        if (ks + 2 < 8) LDFRAG((ks + 2) * 16, aA, bA);
#pragma unroll
        for (int m = 0; m < 2; m++)
#pragma unroll
            for (int nt = 0; nt < 4; nt++)
                mma_f16(acc[m][nt], aB + m * 4, bB + nt * 2);
    }
#undef LDFRAG

    float ls[4][2], lq[4][2];
#pragma unroll
    for (int nt = 0; nt < 4; nt++) { ls[nt][0]=0.f; ls[nt][1]=0.f; lq[nt][0]=0.f; lq[nt][1]=0.f; }

#pragma unroll
    for (int nt = 0; nt < 4; nt++) {
        int col = cwb + nt * 8 + 2 * tg;
        float bx = biasSh[col], by = biasSh[col + 1];
#pragma unroll
        for (int m = 0; m < 2; m++) {
            int r0 = base + rwb + m * 16 + g;
            int r1 = r0 + 8;
            float y00 = acc[m][nt][0] + bx, y01 = acc[m][nt][1] + by;
            float y10 = acc[m][nt][2] + bx, y11 = acc[m][nt][3] + by;
            if (doRelu) {
                y00 = fmaxf(y00, 0.f); y01 = fmaxf(y01, 0.f);
                y10 = fmaxf(y10, 0.f); y11 = fmaxf(y11, 0.f);
            }
            if (r0 < N) {
                ((__half2*)J.Y)[(size_t)r0 * 64 + (col >> 1)] = __floats2half2_rn(y00, y01);
                ls[nt][0] += y00; lq[nt][0] += y00 * y00;
                ls[nt][1] += y01; lq[nt][1] += y01 * y01;
            }
            if (r1 < N) {
                ((__half2*)J.Y)[(size_t)r1 * 64 + (col >> 1)] = __floats2half2_rn(y10, y11);
                ls[nt][0] += y10; lq[nt][0] += y10 * y10;
                ls[nt][1] += y11; lq[nt][1] += y11 * y11;
            }
        }
    }

    if (J.sSout) {
#pragma unroll
        for (int off = 4; off <= 16; off <<= 1)
#pragma unroll
            for (int nt = 0; nt < 4; nt++)
#pragma unroll
                for (int j = 0; j < 2; j++) {
                    ls[nt][j] += __shfl_xor_sync(0xffffffffu, ls[nt][j], off);
                    lq[nt][j] += __shfl_xor_sync(0xffffffffu, lq[nt][j], off);
                }
        if (g == 0) {
#pragma unroll
            for (int nt = 0; nt < 4; nt++)
#pragma unroll
                for (int j = 0; j < 2; j++) {
                    int col = cwb + nt * 8 + 2 * tg + j;
                    atomicAdd(&ssum[col], ls[nt][j]);
                    atomicAdd(&ssq[col],  lq[nt][j]);
                }
        }
        __syncthreads();
        if (t < HD) { atomicAdd(&J.sSout[t], ssum[t]); atomicAdd(&J.sQout[t], ssq[t]); }
    }
}

// ---------------- CSR build ------------------------------------------------------
__global__ void k_hist(const int* __restrict__ row, const int* __restrict__ col, int E) {
    int e = blockIdx.x * blockDim.x + threadIdx.x;
    if (e < E) {
        atomicAdd(&g_cnt2[col[e]], 1);
        atomicAdd(&g_cnt2[MAXN + row[e]], 1);
    }
}

__global__ void __launch_bounds__(1024) k_scan1(int N) {
    __shared__ int wsum[32];
    int t = threadIdx.x;
    int idx = blockIdx.x * 1024 + t;
    int v = (idx < N) ? g_cnt2[idx] : 0;
    int x = v;
#pragma unroll
    for (int off = 1; off < 32; off <<= 1) {
        int y = __shfl_up_sync(0xffffffffu, x, off);
        if ((t & 31) >= off) x += y;
    }
    if ((t & 31) == 31) wsum[t >> 5] = x;
    __syncthreads();
    if (t < 32) {
        int y = wsum[t];
#pragma unroll
        for (int off = 1; off < 32; off <<= 1) {
            int z = __shfl_up_sync(0xffffffffu, y, off);
            if (t >= off) y += z;
        }
        wsum[t] = y;
    }
    __syncthreads();
    int winc = (t >= 32) ? wsum[(t >> 5) - 1] : 0;
    int incl = x + winc;
    if (idx < N) g_rowptr[idx] = incl - v;
    if (t == 1023) g_bsum[blockIdx.x] = incl;
}

// scan finalize + degree init + SELF-ZERO g_cnt2 for the next graph replay
__global__ void __launch_bounds__(1024) k_scanfin(int N, int nb) {
    __shared__ int s[64];
    int t = threadIdx.x;
    if (t < 64) s[t] = (t < nb) ? g_bsum[t] : 0;
    __syncthreads();
    for (int off = 1; off < 64; off <<= 1) {
        int a = (t < 64 && t >= off) ? s[t - off] : 0;
        __syncthreads();
        if (t < 64) s[t] += a;
        __syncthreads();
    }
    int boff = s[blockIdx.x] - g_bsum[blockIdx.x];
    int idx = blockIdx.x * 1024 + t;
    if (idx < N) {
        int r = g_rowptr[idx] + boff;
        g_rowptr[idx] = r;
        g_cursor[idx] = r;
        g_degu[idx] = rsqrtf((float)g_cnt2[MAXN + idx] + 1.f);
        g_degc[idx] = 1.f;
        g_dego[idx] = 1.f;
        g_cnt2[idx] = 0;            // consumed by scan1 — reset for next replay
        g_cnt2[MAXN + idx] = 0;     // consumed just above — reset for next replay
    }
    if (blockIdx.x == 0 && t == 0) g_rowptr[N] = s[63];
}

__global__ void k_fillcsr(const int* __restrict__ row, const int* __restrict__ col, int E) {
    int e = blockIdx.x * blockDim.x + threadIdx.x;
    if (e >= E) return;
    int c = col[e];
    int p = atomicAdd(&g_cursor[c], 1);
    g_er[p] = row[e];
}

// ---------------- CSR gathers (fp16 in AND out), half-warp edge pairing ---------
__global__ void __launch_bounds__(256) k_gather(const __half* __restrict__ lin,
                                                __half* __restrict__ out,
                                                const float* __restrict__ dinv,
                                                const float* __restrict__ b, int N,
                                                float* __restrict__ sS,
                                                float* __restrict__ sQ) {
    __shared__ float ssum[HD], ssq[HD];
    int t = threadIdx.x;
    if (t < HD) { ssum[t] = 0.f; ssq[t] = 0.f; }
    __syncthreads();
    int lane = t & 31, hw = lane >> 4, hl = lane & 15;
    int warpId = (blockIdx.x * blockDim.x + t) >> 5;
    int nW = (blockDim.x * gridDim.x) >> 5;
    float4 bb0 = ((const float4*)b)[hl * 2 + 0];
    float4 bb1 = ((const float4*)b)[hl * 2 + 1];
    float st[8] = {0,0,0,0,0,0,0,0}, qt[8] = {0,0,0,0,0,0,0,0};
    for (int i = warpId; i < N; i += nW) {
        int start = g_rowptr[i], end = g_rowptr[i + 1];
        float di = dinv[i];
        float a[8] = {0,0,0,0,0,0,0,0};
        if (hw == 0) {
            uint4 u = __ldg((const uint4*)(lin + (size_t)i * HD) + hl);
            fma8(a, u, di * di);
        }
        int j0 = start;
        for (; j0 + 32 <= end; j0 += 32) {
            int r = g_er[j0 + lane];
            float dr = dinv[r];
#pragma unroll
            for (int k = 0; k < 16; k++) {
                int src = 2 * k + hw;
                int   rr = __shfl_sync(0xffffffffu, r, src);
                float nn = __shfl_sync(0xffffffffu, dr, src) * di;
                uint4 u = __ldg((const uint4*)(lin + (size_t)rr * HD) + hl);
                fma8(a, u, nn);
            }
        }
        if (j0 < end) {
            int cnt = end - j0;
            int r = 0; float dr = 0.f;
            if (lane < cnt) { r = g_er[j0 + lane]; dr = dinv[r]; }
            int pairs = (cnt + 1) >> 1;
            for (int k = 0; k < pairs; k++) {
                int src = 2 * k + hw;
                int   rr = __shfl_sync(0xffffffffu, r, src);
                float nn = __shfl_sync(0xffffffffu, dr, src) * di;
                if (src < cnt) {
                    uint4 u = __ldg((const uint4*)(lin + (size_t)rr * HD) + hl);
                    fma8(a, u, nn);
                }
            }
        }
#pragma unroll
        for (int j = 0; j < 8; j++)
            a[j] += __shfl_xor_sync(0xffffffffu, a[j], 16);
        if (hw == 0) {
            a[0] = fmaxf(a[0] + bb0.x, 0.f); a[1] = fmaxf(a[1] + bb0.y, 0.f);
            a[2] = fmaxf(a[2] + bb0.z, 0.f); a[3] = fmaxf(a[3] + bb0.w, 0.f);
            a[4] = fmaxf(a[4] + bb1.x, 0.f); a[5] = fmaxf(a[5] + bb1.y, 0.f);
            a[6] = fmaxf(a[6] + bb1.z, 0.f); a[7] = fmaxf(a[7] + bb1.w, 0.f);
            uint2 p0 = pack4(a[0], a[1], a[2], a[3]);
            uint2 p1 = pack4(a[4], a[5], a[6], a[7]);
            ((uint4*)(out + (size_t)i * HD))[hl] = make_uint4(p0.x, p0.y, p1.x, p1.y);
#pragma unroll
            for (int j = 0; j < 8; j++) { st[j] += a[j]; qt[j] += a[j] * a[j]; }
        }
    }
    if (sS) {
        if (hw == 0) {
#pragma unroll
            for (int j = 0; j < 8; j++) {
                atomicAdd(&ssum[hl * 8 + j], st[j]);
                atomicAdd(&ssq[hl * 8 + j],  qt[j]);
            }
        }
        __syncthreads();
        if (t < HD) { atomicAdd(&sS[t], ssum[t]); atomicAdd(&sQ[t], ssq[t]); }
    }
}

// weighted ctx/obj gather with inline edge softmax from g_ed
__global__ void __launch_bounds__(256) k_gather2(const __half* __restrict__ linC,
                                                 const __half* __restrict__ linO,
                                                 __half* __restrict__ outC,
                                                 __half* __restrict__ outO,
                                                 const float* __restrict__ dc,
                                                 const float* __restrict__ dd,
                                                 const float* __restrict__ bc,
                                                 const float* __restrict__ bo,
                                                 const float* __restrict__ bea, int N,
                                                 float* sSc, float* sQc,
                                                 float* sSo, float* sQo) {
    __shared__ float red[4][HD];
    int t = threadIdx.x;
    for (int i = t; i < 4 * HD; i += blockDim.x) ((float*)red)[i] = 0.f;
    __syncthreads();
    int lane = t & 31, hw = lane >> 4, hl = lane & 15;
    int warpId = (blockIdx.x * blockDim.x + t) >> 5;
    int nW = (blockDim.x * gridDim.x) >> 5;
    float bead = bea[1] - bea[0];
    float4 bc0 = ((const float4*)bc)[hl * 2 + 0];
    float4 bc1 = ((const float4*)bc)[hl * 2 + 1];
    float4 bo0 = ((const float4*)bo)[hl * 2 + 0];
    float4 bo1 = ((const float4*)bo)[hl * 2 + 1];
    float stc[8] = {0,0,0,0,0,0,0,0}, qtc[8] = {0,0,0,0,0,0,0,0};
    float sto[8] = {0,0,0,0,0,0,0,0}, qto[8] = {0,0,0,0,0,0,0,0};
    for (int i = warpId; i < N; i += nW) {
        int start = g_rowptr[i], end = g_rowptr[i + 1];
        float dci = rsqrtf(dc[i]), doi = rsqrtf(dd[i]);
        float edyi = g_ed[i].y + bead;
        float aC[8] = {0,0,0,0,0,0,0,0}, aO[8] = {0,0,0,0,0,0,0,0};
        if (hw == 0) {
            uint4 u = __ldg((const uint4*)(linC + (size_t)i * HD) + hl);
            fma8(aC, u, dci * dci);
        } else {
            uint4 u = __ldg((const uint4*)(linO + (size_t)i * HD) + hl);
            fma8(aO, u, doi * doi);
        }
        int j0 = start;
        for (; j0 + 32 <= end; j0 += 32) {
            int r = g_er[j0 + lane];
            float2 ed = __ldg(&g_ed[r]);
            float delta = edyi + ed.x;
            float s1 = 1.f / (1.f + expf(-delta));
            float s0 = 1.f - s1;
            float wc = rsqrtf(dc[r]) * s0;
            float wo = rsqrtf(dd[r]) * s1;
#pragma unroll
            for (int k = 0; k < 16; k++) {
                int src = 2 * k + hw;
                int   rr = __shfl_sync(0xffffffffu, r, src);
                float nc = __shfl_sync(0xffffffffu, wc, src) * dci;
                float no = __shfl_sync(0xffffffffu, wo, src) * doi;
                uint4 uC = __ldg((const uint4*)(linC + (size_t)rr * HD) + hl);
                uint4 uO = __ldg((const uint4*)(linO + (size_t)rr * HD) + hl);
                fma8(aC, uC, nc);
                fma8(aO, uO, no);
            }
        }
        if (j0 < end) {
            int cnt = end - j0;
            int r = 0; float wc = 0.f, wo = 0.f;
            if (lane < cnt) {
                r = g_er[j0 + lane];
                float2 ed = __ldg(&g_ed[r]);
                float delta = edyi + ed.x;
                float s1 = 1.f / (1.f + expf(-delta));
                float s0 = 1.f - s1;
                wc = rsqrtf(dc[r]) * s0;
                wo = rsqrtf(dd[r]) * s1;
            }
            int pairs = (cnt + 1) >> 1;
            for (int k = 0; k < pairs; k++) {
                int src = 2 * k + hw;
                int   rr = __shfl_sync(0xffffffffu, r, src);
                float nc = __shfl_sync(0xffffffffu, wc, src) * dci;
                float no = __shfl_sync(0xffffffffu, wo, src) * doi;
                if (src < cnt) {
                    uint4 uC = __ldg((const uint4*)(linC + (size_t)rr * HD) + hl);
                    uint4 uO = __ldg((const uint4*)(linO + (size_t)rr * HD) + hl);
                    fma8(aC, uC, nc);
                    fma8(aO, uO, no);
                }
            }
        }
#pragma unroll
        for (int j = 0; j < 8; j++) {
            aC[j] += __shfl_xor_sync(0xffffffffu, aC[j], 16);
            aO[j] += __shfl_xor_sync(0xffffffffu, aO[j], 16);
        }
        if (hw == 0) {
            aC[0] = fmaxf(aC[0] + bc0.x, 0.f); aC[1] = fmaxf(aC[1] + bc0.y, 0.f);
            aC[2] = fmaxf(aC[2] + bc0.z, 0.f); aC[3] = fmaxf(aC[3] + bc0.w, 0.f);
            aC[4] = fmaxf(aC[4] + bc1.x, 0.f); aC[5] = fmaxf(aC[5] + bc1.y, 0.f);
            aC[6] = fmaxf(aC[6] + bc1.z, 0.f); aC[7] = fmaxf(aC[7] + bc1.w, 0.f);
            aO[0] = fmaxf(aO[0] + bo0.x, 0.f); aO[1] = fmaxf(aO[1] + bo0.y, 0.f);
            aO[2] = fmaxf(aO[2] + bo0.z, 0.f); aO[3] = fmaxf(aO[3] + bo0.w, 0.f);
            aO[4] = fmaxf(aO[4] + bo1.x, 0.f); aO[5] = fmaxf(aO[5] + bo1.y, 0.f);
            aO[6] = fmaxf(aO[6] + bo1.z, 0.f); aO[7] = fmaxf(aO[7] + bo1.w, 0.f);
            uint2 c0 = pack4(aC[0], aC[1], aC[2], aC[3]);
            uint2 c1 = pack4(aC[4], aC[5], aC[6], aC[7]);
            uint2 o0 = pack4(aO[0], aO[1], aO[2], aO[3]);
            uint2 o1 = pack4(aO[4], aO[5], aO[6], aO[7]);
            ((uint4*)(outC + (size_t)i * HD))[hl] = make_uint4(c0.x, c0.y, c1.x, c1.y);
            ((uint4*)(outO + (size_t)i * HD))[hl] = make_uint4(o0.x, o0.y, o1.x, o1.y);
#pragma unroll
            for (int j = 0; j < 8; j++) {
                stc[j] += aC[j]; qtc[j] += aC[j] * aC[j];
                sto[j] += aO[j]; qto[j] += aO[j] * aO[j];
            }
        }
    }
    if (hw == 0) {
#pragma unroll
        for (int j = 0; j < 8; j++) {
            atomicAdd(&red[0][hl * 8 + j], stc[j]);
            atomicAdd(&red[1][hl * 8 + j], qtc[j]);
            atomicAdd(&red[2][hl * 8 + j], sto[j]);
            atomicAdd(&red[3][hl * 8 + j], qto[j]);
        }
    }
    __syncthreads();
    if (t < HD) {
        atomicAdd(&sSc[t], red[0][t]); atomicAdd(&sQc[t], red[1][t]);
        atomicAdd(&sSo[t], red[2][t]); atomicAdd(&sQo[t], red[3][t]);
    }
}

// ---------------- attention node pass ---------------------------------------------
__global__ void k_att_node(const __half* __restrict__ h,
                           const float* __restrict__ Wna, const float* __restrict__ bna,
                           const float* __restrict__ Wea,
                           __half* __restrict__ xc, __half* __restrict__ xo, int N,
                           float* sSc, float* sQc, float* sSo, float* sQo) {
    __shared__ float Wc[HD * 6];
    __shared__ float red[4][HD];
    int t = threadIdx.x;
    for (int i = t; i < HD * 6; i += blockDim.x) {
        int k = i / 6, j = i % 6;
        float v;
        if (j < 2)      v = Wna[k * 2 + j];
        else if (j < 4) v = Wea[k * 2 + (j - 2)];
        else            v = Wea[(HD + k) * 2 + (j - 4)];
        Wc[i] = v;
    }
    for (int i = t; i < 4 * HD; i += blockDim.x) ((float*)red)[i] = 0.f;
    __syncthreads();
    int warps = (blockDim.x * gridDim.x) >> 5;
    int gw = (blockIdx.x * blockDim.x + t) >> 5;
    int l  = t & 31;
    float b0 = bna[0], b1 = bna[1];
    float sc[4]={0,0,0,0}, qc[4]={0,0,0,0}, so[4]={0,0,0,0}, qo[4]={0,0,0,0};
    for (int i = gw; i < N; i += warps) {
        float4 hv = unpack4(((const uint2*)(h + (size_t)i * HD))[l]);
        float p[6];
#pragma unroll
        for (int j = 0; j < 6; j++) {
            p[j] = hv.x * Wc[(4*l+0)*6 + j] + hv.y * Wc[(4*l+1)*6 + j]
                 + hv.z * Wc[(4*l+2)*6 + j] + hv.w * Wc[(4*l+3)*6 + j];
        }
#pragma unroll
        for (int off = 16; off; off >>= 1)
#pragma unroll
            for (int j = 0; j < 6; j++)
                p[j] += __shfl_xor_sync(0xffffffffu, p[j], off);
        float l0 = p[0] + b0, l1 = p[1] + b1;
        float m  = fmaxf(l0, l1);
        float e0 = expf(l0 - m), e1 = expf(l1 - m);
        float inv = 1.f / (e0 + e1);
        float a0 = e0 * inv, a1 = e1 * inv;
        float4 vc = make_float4(hv.x*a0, hv.y*a0, hv.z*a0, hv.w*a0);
        float4 vo = make_float4(hv.x*a1, hv.y*a1, hv.z*a1, hv.w*a1);
        ((uint2*)(xc + (size_t)i * HD))[l] = pack4(vc.x, vc.y, vc.z, vc.w);
        ((uint2*)(xo + (size_t)i * HD))[l] = pack4(vo.x, vo.y, vo.z, vo.w);
        sc[0]+=vc.x; qc[0]+=vc.x*vc.x; sc[1]+=vc.y; qc[1]+=vc.y*vc.y;
        sc[2]+=vc.z; qc[2]+=vc.z*vc.z; sc[3]+=vc.w; qc[3]+=vc.w*vc.w;
        so[0]+=vo.x; qo[0]+=vo.x*vo.x; so[1]+=vo.y; qo[1]+=vo.y*vo.y;
        so[2]+=vo.z; qo[2]+=vo.z*vo.z; so[3]+=vo.w; qo[3]+=vo.w*vo.w;
        if (l == 0) g_ed[i] = make_float2(p[3] - p[2], p[5] - p[4]);
    }
#pragma unroll
    for (int j = 0; j < 4; j++) {
        atomicAdd(&red[0][l*4+j], sc[j]);
        atomicAdd(&red[1][l*4+j], qc[j]);
        atomicAdd(&red[2][l*4+j], so[j]);
        atomicAdd(&red[3][l*4+j], qo[j]);
    }
    __syncthreads();
    if (t < HD) {
        atomicAdd(&sSc[t], red[0][t]); atomicAdd(&sQc[t], red[1][t]);
        atomicAdd(&sSo[t], red[2][t]); atomicAdd(&sQo[t], red[3][t]);
    }
}

__global__ void k_att_edge(const int* __restrict__ row, const int* __restrict__ col,
                           const float* __restrict__ bea, int E) {
    int e = blockIdx.x * blockDim.x + threadIdx.x;
    if (e >= E) return;
    int r = row[e], c = col[e];
    float delta = (bea[1] - bea[0]) + g_ed[r].x + g_ed[c].y;
    float a1 = 1.f / (1.f + expf(-delta));
    float a0 = 1.f - a1;
    atomicAdd(&g_degc[r], a0);
    atomicAdd(&g_dego[r], a1);
}

__global__ void k_permadd_stats(const __half* __restrict__ xc, const __half* __restrict__ xo,
                                const int* __restrict__ perm, __half* __restrict__ z, int N,
                                float* __restrict__ sS, float* __restrict__ sQ) {
    __shared__ float ssum[HD], ssq[HD];
    int t = threadIdx.x;
    if (t < HD) { ssum[t] = 0.f; ssq[t] = 0.f; }
    __syncthreads();
    int total  = N * HD4;
    int stride = blockDim.x * gridDim.x;
    int idx    = blockIdx.x * blockDim.x + t;
    int fb     = (idx & 31) * 4;
    float a0=0,a1=0,a2=0,a3=0,q0=0,q1=0,q2=0,q3=0;
    for (; idx < total; idx += stride) {
        int i = idx >> 5, l = idx & 31;
        int p = perm[i];
        float4 a = unpack4(((const uint2*)(xc + (size_t)p * HD))[l]);
        float4 b = unpack4(((const uint2*)xo)[idx]);
        a.x += b.x; a.y += b.y; a.z += b.z; a.w += b.w;
        ((uint2*)z)[idx] = pack4(a.x, a.y, a.z, a.w);
        a0 += a.x; q0 += a.x*a.x; a1 += a.y; q1 += a.y*a.y;
        a2 += a.z; q2 += a.z*a.z; a3 += a.w; q3 += a.w*a.w;
    }
    atomicAdd(&ssum[fb+0], a0); atomicAdd(&ssq[fb+0], q0);
    atomicAdd(&ssum[fb+1], a1); atomicAdd(&ssq[fb+1], q1);
    atomicAdd(&ssum[fb+2], a2); atomicAdd(&ssq[fb+2], q2);
    atomicAdd(&ssum[fb+3], a3); atomicAdd(&ssq[fb+3], q3);
    __syncthreads();
    if (t < HD) { atomicAdd(&sS[t], ssum[t]); atomicAdd(&sQ[t], ssq[t]); }
}

// ---------------- [N,128]x[128,10] + log_softmax (fp16 Z), batched --------------
__global__ void k_gemm2_lsm(LJobs jobs, int N, float invN) {
    __shared__ float Ws[HD * 10];
    __shared__ float bs[10];
    __shared__ float scaleSh[HD], tshSh[HD];
    const LJob J = jobs.j[blockIdx.y];
    int t = threadIdx.x;
    if (t < HD) {
        float mu  = J.sSin[t] * invN;
        float var = fmaxf(J.sQin[t] * invN - mu * mu, 0.f);
        float rs  = rsqrtf(var + 1e-5f);
        scaleSh[t] = rs;
        tshSh[t]   = 1e-4f / rs - mu;
    }
    __syncthreads();
    for (int i = t; i < HD * 10; i += blockDim.x)
        Ws[i] = scaleSh[i / 10] * J.W[i];
    __syncthreads();
    if (t < 160) {
        int j = t / 16, seg = t % 16;
        float part = 0.f;
#pragma unroll
        for (int k = 0; k < 8; k++) {
            int kk = seg * 8 + k;
            part += tshSh[kk] * Ws[kk * 10 + j];
        }
#pragma unroll
        for (int off = 8; off; off >>= 1)
            part += __shfl_down_sync(0xffffffffu, part, off, 16);
        if (seg == 0) bs[j] = J.b[j] + part;
    }
    __syncthreads();
    int warps = (blockDim.x * gridDim.x) >> 5;
    int gw = (blockIdx.x * blockDim.x + t) >> 5;
    int l  = t & 31;
    for (int i = gw; i < N; i += warps) {
        float4 z = unpack4(((const uint2*)(J.Z + (size_t)i * HD))[l]);
        float p[10];
#pragma unroll
        for (int j = 0; j < 10; j++) {
            p[j] = z.x * Ws[(4*l+0)*10 + j] + z.y * Ws[(4*l+1)*10 + j]
                 + z.z * Ws[(4*l+2)*10 + j] + z.w * Ws[(4*l+3)*10 + j];
        }
#pragma unroll
        for (int off = 16; off; off >>= 1)
#pragma unroll
            for (int j = 0; j < 10; j++)
                p[j] += __shfl_xor_sync(0xffffffffu, p[j], off);
        float m = -1e30f;
#pragma unroll
        for (int j = 0; j < 10; j++) { p[j] += bs[j]; m = fmaxf(m, p[j]); }
        float s = 0.f;
#pragma unroll
        for (int j = 0; j < 10; j++) s += expf(p[j] - m);
        float lse = m + logf(s);
        if (l < 10) J.out[(size_t)i * 10 + l] = p[l] - lse;
    }
}

// ---------------- host orchestration ------------------------------------------------
extern "C" void kernel_launch(void* const* d_in, const int* in_sizes, int n_in,
                              void* d_out, int out_size) {
    const float* x      = (const float*)d_in[0];
    const int*   ei     = (const int*)  d_in[1];
    const int*   perm   = (const int*)  d_in[2];
    const float* W_feat = (const float*)d_in[3];
    const float* b_feat = (const float*)d_in[4];
    const float* W_convs= (const float*)d_in[5];
    const float* b_convs= (const float*)d_in[6];
    const float* W_ea   = (const float*)d_in[7];
    const float* b_ea   = (const float*)d_in[8];
    const float* W_na   = (const float*)d_in[9];
    const float* b_na   = (const float*)d_in[10];
    const float* W_ctx  = (const float*)d_in[11];
    const float* b_ctx  = (const float*)d_in[12];
    const float* W_obj  = (const float*)d_in[13];
    const float* b_obj  = (const float*)d_in[14];
    const float* W_fc1  = (const float*)d_in[15];
    const float* b_fc1  = (const float*)d_in[16];
    const float* W_fc2  = (const float*)d_in[17];
    const float* b_fc2  = (const float*)d_in[18];

    int N = in_sizes[0] / HD;
    int E = in_sizes[1] / 2;
    const int* row = ei;
    const int* col = ei + E;
    float* out = (float*)d_out;

    static cudaStream_t sB = nullptr;
    static cudaEvent_t ev0, evCSR, ev1, evAE;
    if (!sB) {
        cudaStreamCreateWithFlags(&sB, cudaStreamNonBlocking);
        cudaEventCreateWithFlags(&ev0,   cudaEventDisableTiming);
        cudaEventCreateWithFlags(&evCSR, cudaEventDisableTiming);
        cudaEventCreateWithFlags(&ev1,   cudaEventDisableTiming);
        cudaEventCreateWithFlags(&evAE,  cudaEventDisableTiming);
    }

    float* Bbase = nullptr;
    cudaGetSymbolAddress((void**)&Bbase, g_B);
    __half* H0 = (__half*)(Bbase + 0 * (size_t)MAXN * HD);
    __half* H1 = (__half*)(Bbase + 1 * (size_t)MAXN * HD);
    __half* H2 = (__half*)(Bbase + 2 * (size_t)MAXN * HD);
    __half* H3 = (__half*)(Bbase + 3 * (size_t)MAXN * HD);
    __half* H4 = (__half*)(Bbase + 4 * (size_t)MAXN * HD);
    __half* H5 = (__half*)(Bbase + 5 * (size_t)MAXN * HD);
    float *degup, *degcp, *degop, *statsp;
    cudaGetSymbolAddress((void**)&degup,  g_degu);
    cudaGetSymbolAddress((void**)&degcp,  g_degc);
    cudaGetSymbolAddress((void**)&degop,  g_dego);
    cudaGetSymbolAddress((void**)&statsp, g_stats);
    auto S = [&](int i) { return statsp + i * HD; };
    auto Q = [&](int i) { return statsp + (NSLOT + i) * HD; };

    const int gemm_smem = 2 * 128 * AS * (int)sizeof(__half);
    cudaFuncSetAttribute(k_gemm_tc, cudaFuncAttributeMaxDynamicSharedMemorySize, gemm_smem);

    int gbGemm = (N + 127) / 128;
    int gbE    = (E + 255) / 256;
    int nb     = (N + 1023) / 1024;
    float invN = 1.f / (float)N;

    auto gemm1 = [&](const void* X, __half* Y, const float* W, const float* b,
                     int sin, int sout, int relu, int inHalf) {
        GJobs js{};
        js.j[0] = {X, Y, W, b, S(sin), Q(sin),
                   sout >= 0 ? S(sout) : nullptr, sout >= 0 ? Q(sout) : nullptr};
        k_gemm_tc<<<dim3(gbGemm, 1), 512, gemm_smem>>>(js, N, relu, inHalf, invN);
    };

    // ---- fork: CSR build on side stream (cnt2 pre-zeroed by prior replay) ----
    cudaEventRecord(ev0, 0);
    cudaStreamWaitEvent(sB, ev0, 0);
    k_hist<<<gbE, 256, 0, sB>>>(row, col, E);
    k_scan1<<<nb, 1024, 0, sB>>>(N);
    k_scanfin<<<nb, 1024, 0, sB>>>(N, nb);
    k_fillcsr<<<gbE, 256, 0, sB>>>(row, col, E);
    cudaEventRecord(evCSR, sB);

    // main
    cudaMemsetAsync(statsp, 0, 2 * NSLOT * HD * sizeof(float), 0);
    k_stats<<<512, 256>>>(x, N, S(0), Q(0));
    gemm1(x, H2, W_feat, b_feat, 0, 1, 1, 0);
    gemm1(H2, H1, W_convs + 0 * HD * HD, nullptr, 1, -1, 0, 1);

    cudaStreamWaitEvent(0, evCSR, 0);
    k_gather<<<1024, 256>>>(H1, H0, degup, b_convs + 0 * HD, N, S(2), Q(2));
    gemm1(H0, H1, W_convs + 1 * HD * HD, nullptr, 2, -1, 0, 1);
    k_gather<<<1024, 256>>>(H1, H2, degup, b_convs + 1 * HD, N, S(3), Q(3));
    gemm1(H2, H1, W_convs + 2 * HD * HD, nullptr, 3, -1, 0, 1);
    k_gather<<<1024, 256>>>(H1, H0, degup, b_convs + 2 * HD, N, nullptr, nullptr);

    // attention node projections
    k_att_node<<<256, 256>>>(H0, W_na, b_na, W_ea, H2, H3, N, S(4), Q(4), S(5), Q(5));

    // fork: att-weighted degree sums on side stream
    cudaEventRecord(ev1, 0);
    cudaStreamWaitEvent(sB, ev1, 0);
    k_att_edge<<<gbE, 256, 0, sB>>>(row, col, b_ea, E);
    cudaEventRecord(evAE, sB);

    {
        GJobs js{};
        js.j[0] = {H2, H1, W_ctx, nullptr, S(4), Q(4), nullptr, nullptr};
        js.j[1] = {H3, H5, W_obj, nullptr, S(5), Q(5), nullptr, nullptr};
        k_gemm_tc<<<dim3(gbGemm, 2), 512, gemm_smem>>>(js, N, 0, 1, invN);
    }
    cudaStreamWaitEvent(0, evAE, 0);
    k_gather2<<<1024, 256>>>(H1, H5, H4, H3, degcp, degop, b_ctx, b_obj, b_ea, N,
                             S(6), Q(6), S(7), Q(7));

    k_permadd_stats<<<256, 256>>>(H4, H3, perm, H1, N, S(11), Q(11));

    {
        GJobs js{};
        js.j[0] = {H4, H0, W_fc1 + 0 * HD * HD, b_fc1 + 0 * HD, S(6),  Q(6),  S(8),  Q(8)};
        js.j[1] = {H3, H5, W_fc1 + 1 * HD * HD, b_fc1 + 1 * HD, S(7),  Q(7),  S(9),  Q(9)};
        js.j[2] = {H1, H2, W_fc1 + 2 * HD * HD, b_fc1 + 2 * HD, S(11), Q(11), S(10), Q(10)};
        k_gemm_tc<<<dim3(gbGemm, 3), 512, gemm_smem>>>(js, N, 1, 1, invN);
    }
    {
        LJobs js{};
        js.j[0] = {H0, out,                      W_fc2 + 0 * HD * 10, b_fc2 + 0 * 10, S(8),  Q(8)};
        js.j[1] = {H5, out + (size_t)N * 10,     W_fc2 + 1 * HD * 10, b_fc2 + 1 * 10, S(9),  Q(9)};
        js.j[2] = {H2, out + (size_t)2 * N * 10, W_fc2 + 2 * HD * 10, b_fc2 + 2 * 10, S(10), Q(10)};
        k_gemm2_lsm<<<dim3(512, 3), 256>>>(js, N, invN);
    }
}